// round 3
// baseline (speedup 1.0000x reference)
#include <cuda_runtime.h>
#include <cstdint>
#include <cstddef>

typedef unsigned long long u64;

#define L_TOT 4096
#define NN    64
#define TCH   32
#define NCH   128

// ---------------- scratch (device globals; no runtime allocation) ----------------
__device__ __align__(256) float g_At[L_TOT * NN * NN];   // g_At[t*4096 + k*64 + i] = A[t][i][k]
__device__ __align__(256) float g_W0[NCH * NN * 128];    // chunk affine maps [Y|M], ping
__device__ __align__(256) float g_W1[NCH * NN * 128];    // pong

// warp -> row-tile permutation; per-SMSP sums of ti are all 30 (balanced triangular work)
__constant__ int TI_TAB[16] = {0,1,2,3, 5,4,7,6, 10,11,8,9, 15,14,13,12};

// ---------------- f32x2 helpers ----------------
__device__ __forceinline__ u64 pk2(float lo, float hi){
  u64 r; asm("mov.b64 %0, {%1,%2};" : "=l"(r) : "f"(lo), "f"(hi)); return r;
}
__device__ __forceinline__ u64 dup2(float v){
  u64 r; asm("mov.b64 %0, {%1,%1};" : "=l"(r) : "f"(v)); return r;
}
__device__ __forceinline__ void fma2(u64 &d, u64 a, u64 b){
  asm("fma.rn.f32x2 %0, %1, %2, %0;" : "+l"(d) : "l"(a), "l"(b));
}
__device__ __forceinline__ void add2(u64 &d, u64 a){
  asm("add.rn.f32x2 %0, %0, %1;" : "+l"(d) : "l"(a));
}
__device__ __forceinline__ void unpk2(u64 v, float &lo, float &hi){
  asm("mov.b64 {%0,%1}, %2;" : "=f"(lo), "=f"(hi) : "l"(v));
}

// ================= prep: transpose every A[t] (64x64) into g_At =================
__global__ void prep_kernel(const float* __restrict__ A){
  __shared__ float s[64 * 65];
  const int t = blockIdx.x;
  const float* src = A + (size_t)t * 4096;
  float* dst = g_At + (size_t)t * 4096;
  // load: s[i*65 + k] = A[t][i][k]; vector LDG, scalar STS (stride 65 is not
  // 16B-aligned, so no vector STS here — that was the R2 misaligned-address bug)
  for (int idx = threadIdx.x; idx < 1024; idx += 256){
    int i = idx >> 4, k0 = (idx & 15) << 2;
    float4 v = *(const float4*)(src + i * 64 + k0);
    float* p = s + i * 65 + k0;
    p[0] = v.x; p[1] = v.y; p[2] = v.z; p[3] = v.w;
  }
  __syncthreads();
  // store: g_At[t][k][i] = s[i*65 + k]  (conflict-free reads: bank = (i+k) mod 32)
  for (int idx = threadIdx.x; idx < 1024; idx += 256){
    int k = idx >> 4, i0 = (idx & 15) << 2;
    float4 v;
    v.x = s[(i0 + 0) * 65 + k];
    v.y = s[(i0 + 1) * 65 + k];
    v.z = s[(i0 + 2) * 65 + k];
    v.w = s[(i0 + 3) * 65 + k];
    *(float4*)(dst + k * 64 + i0) = v;
  }
}

// ================= pass1: per-chunk affine map W = [Y | M] =================
// W update per step: W <- A_t * W ; Y-half gets += B_t (outer) inp_t
__global__ void __launch_bounds__(512, 1)
pass1_kernel(const float* __restrict__ inp, const float* __restrict__ Bst){
  extern __shared__ float sm[];
  float* Atr  = sm;                    // [64][68]  Atr[k*68+i] = A[t][i][k]
  float* Wb   = Atr + 64 * 68;         // [2][64][132]
  float* sInp = Wb + 2 * 64 * 132;     // [64]
  float* sBst = sInp + 64;             // [64]

  const int c = blockIdx.x, tid = threadIdx.x;
  const int w = tid >> 5, lane = tid & 31;
  const int ti = TI_TAB[w], i0 = ti << 2, klen = i0 + 4, c0 = lane << 2;

  for (int idx = tid; idx < 2 * 64 * 132; idx += 512) Wb[idx] = 0.0f;
  __syncthreads();
  if (tid < 64) Wb[tid * 132 + 64 + tid] = 1.0f;   // M = I in buffer 0

  int cur = 0;
  const int t0 = c * TCH;
  for (int s = 0; s < TCH; ++s){
    __syncthreads();
    const int t = t0 + s;
    const float* At = g_At + (size_t)t * 4096;
    for (int idx = tid; idx < 1024; idx += 512){
      int k = idx >> 4, j0 = (idx & 15) << 2;
      *(float4*)(Atr + k * 68 + j0) = *(const float4*)(At + k * 64 + j0);
    }
    if (tid < 64)       sInp[tid]      = inp[(size_t)t * 64 + tid];
    else if (tid < 128) sBst[tid - 64] = Bst[(size_t)t * 64 + tid - 64];
    __syncthreads();

    const float* Win  = Wb + cur * (64 * 132);
    float*       Wout = Wb + (cur ^ 1) * (64 * 132);

    u64 a00 = 0, a01 = 0, a10 = 0, a11 = 0, a20 = 0, a21 = 0, a30 = 0, a31 = 0;
#pragma unroll 4
    for (int k = 0; k < klen; ++k){
      float4 av = *(const float4*)(Atr + k * 68 + i0);   // warp broadcast
      u64 b0 = dup2(av.x), b1 = dup2(av.y), b2 = dup2(av.z), b3 = dup2(av.w);
      ulonglong2 wv = *(const ulonglong2*)(Win + k * 132 + c0);
      fma2(a00, b0, wv.x); fma2(a01, b0, wv.y);
      fma2(a10, b1, wv.x); fma2(a11, b1, wv.y);
      fma2(a20, b2, wv.x); fma2(a21, b2, wv.y);
      fma2(a30, b3, wv.x); fma2(a31, b3, wv.y);
    }

    if (c0 < 64){   // rank-1 input injection on the Y half
      u64 ipa = pk2(sInp[c0],     sInp[c0 + 1]);
      u64 ipb = pk2(sInp[c0 + 2], sInp[c0 + 3]);
      u64 q;
      q = dup2(sBst[i0 + 0]); fma2(a00, q, ipa); fma2(a01, q, ipb);
      q = dup2(sBst[i0 + 1]); fma2(a10, q, ipa); fma2(a11, q, ipb);
      q = dup2(sBst[i0 + 2]); fma2(a20, q, ipa); fma2(a21, q, ipb);
      q = dup2(sBst[i0 + 3]); fma2(a30, q, ipa); fma2(a31, q, ipb);
    }

    ulonglong2 v;
    v.x = a00; v.y = a01; *(ulonglong2*)(Wout + (i0 + 0) * 132 + c0) = v;
    v.x = a10; v.y = a11; *(ulonglong2*)(Wout + (i0 + 1) * 132 + c0) = v;
    v.x = a20; v.y = a21; *(ulonglong2*)(Wout + (i0 + 2) * 132 + c0) = v;
    v.x = a30; v.y = a31; *(ulonglong2*)(Wout + (i0 + 3) * 132 + c0) = v;
    cur ^= 1;
  }

  __syncthreads();
  const float* Wf = Wb + cur * (64 * 132);
  float* dst = g_W0 + (size_t)c * 8192;
  for (int idx = tid; idx < 2048; idx += 512){
    int n = idx >> 5, q = (idx & 31) << 2;
    *(float4*)(dst + n * 128 + q) = *(const float4*)(Wf + n * 132 + q);
  }
}

// ================= scan: Kogge-Stone over affine maps =================
// dst[c] = src[c] o src[c-d] : (M2@M1, M2@Y1 + Y2); M stays lower-triangular.
__global__ void __launch_bounds__(512, 1)
scan_kernel(int d, int src_w0){
  const float* src = src_w0 ? g_W0 : g_W1;
  float*       dst = src_w0 ? g_W1 : g_W0;
  const int c = blockIdx.x, tid = threadIdx.x;

  if (c < d){
    const float* s = src + (size_t)c * 8192;
    float*       o = dst + (size_t)c * 8192;
    for (int idx = tid; idx < 2048; idx += 512)
      *(float4*)(o + idx * 4) = *(const float4*)(s + idx * 4);
    return;
  }

  extern __shared__ float sm[];
  float* Mtr  = sm;                 // [64][68]  Mtr[k*68+i] = M_later[i][k]
  float* Wbuf = Mtr + 64 * 68;      // [64][132] earlier [Y1|M1]
  float* Y2   = Wbuf + 64 * 132;    // [64][68]  later Y

  const float* later   = src + (size_t)c * 8192;
  const float* earlier = src + (size_t)(c - d) * 8192;

  for (int idx = tid; idx < 4096; idx += 512){
    int i = idx >> 6, k = idx & 63;
    Mtr[k * 68 + i] = later[i * 128 + 64 + k];
  }
  for (int idx = tid; idx < 1024; idx += 512){
    int i = idx >> 4, q = (idx & 15) << 2;
    *(float4*)(Y2 + i * 68 + q) = *(const float4*)(later + i * 128 + q);
  }
  for (int idx = tid; idx < 2048; idx += 512){
    int n = idx >> 5, q = (idx & 31) << 2;
    *(float4*)(Wbuf + n * 132 + q) = *(const float4*)(earlier + n * 128 + q);
  }
  __syncthreads();

  const int w = tid >> 5, lane = tid & 31;
  const int ti = TI_TAB[w], i0 = ti << 2, klen = i0 + 4, c0 = lane << 2;

  u64 a00 = 0, a01 = 0, a10 = 0, a11 = 0, a20 = 0, a21 = 0, a30 = 0, a31 = 0;
#pragma unroll 4
  for (int k = 0; k < klen; ++k){
    float4 av = *(const float4*)(Mtr + k * 68 + i0);
    u64 b0 = dup2(av.x), b1 = dup2(av.y), b2 = dup2(av.z), b3 = dup2(av.w);
    ulonglong2 wv = *(const ulonglong2*)(Wbuf + k * 132 + c0);
    fma2(a00, b0, wv.x); fma2(a01, b0, wv.y);
    fma2(a10, b1, wv.x); fma2(a11, b1, wv.y);
    fma2(a20, b2, wv.x); fma2(a21, b2, wv.y);
    fma2(a30, b3, wv.x); fma2(a31, b3, wv.y);
  }

  if (c0 < 64){   // + Y2 on the Y half
    ulonglong2 yv;
    yv = *(const ulonglong2*)(Y2 + (i0 + 0) * 68 + c0); add2(a00, yv.x); add2(a01, yv.y);
    yv = *(const ulonglong2*)(Y2 + (i0 + 1) * 68 + c0); add2(a10, yv.x); add2(a11, yv.y);
    yv = *(const ulonglong2*)(Y2 + (i0 + 2) * 68 + c0); add2(a20, yv.x); add2(a21, yv.y);
    yv = *(const ulonglong2*)(Y2 + (i0 + 3) * 68 + c0); add2(a30, yv.x); add2(a31, yv.y);
  }

  float* o = dst + (size_t)c * 8192;
  ulonglong2 v;
  v.x = a00; v.y = a01; *(ulonglong2*)(o + (i0 + 0) * 128 + c0) = v;
  v.x = a10; v.y = a11; *(ulonglong2*)(o + (i0 + 1) * 128 + c0) = v;
  v.x = a20; v.y = a21; *(ulonglong2*)(o + (i0 + 2) * 128 + c0) = v;
  v.x = a30; v.y = a31; *(ulonglong2*)(o + (i0 + 3) * 128 + c0) = v;
}

// ================= pass3: re-run recurrence with carries, write out =================
__global__ void __launch_bounds__(512, 1)
pass3_kernel(const float* __restrict__ inp, const float* __restrict__ Bst,
             float* __restrict__ out){
  extern __shared__ float sm[];
  float* Atr  = sm;                    // [64][68]
  float* Xb   = Atr + 64 * 68;         // [2][64][68]   state X[n][b]
  float* Ost  = Xb + 2 * 64 * 68;      // [64][65]      output transpose stage
  float* sInp = Ost + 64 * 65;         // [64]
  float* sBst = sInp + 64;             // [64]

  const int c = blockIdx.x, tid = threadIdx.x;
  const int w = tid >> 5, lane = tid & 31;
  const int ti = TI_TAB[w], i0 = ti << 2, klen = i0 + 4, c0 = lane << 1;

  // init X = Y of scanned prefix (chunk c-1), or 0 for chunk 0
  if (c == 0){
    for (int idx = tid; idx < 64 * 68; idx += 512) Xb[idx] = 0.0f;
  } else {
    const float* Yp = g_W1 + (size_t)(c - 1) * 8192;
    for (int idx = tid; idx < 1024; idx += 512){
      int n = idx >> 4, q = (idx & 15) << 2;
      *(float4*)(Xb + n * 68 + q) = *(const float4*)(Yp + n * 128 + q);
    }
  }

  int cur = 0;
  const int t0 = c * TCH;
  for (int s = 0; s < TCH; ++s){
    __syncthreads();
    const int t = t0 + s;
    const float* At = g_At + (size_t)t * 4096;
    for (int idx = tid; idx < 1024; idx += 512){
      int k = idx >> 4, j0 = (idx & 15) << 2;
      *(float4*)(Atr + k * 68 + j0) = *(const float4*)(At + k * 64 + j0);
    }
    if (tid < 64)       sInp[tid]      = inp[(size_t)t * 64 + tid];
    else if (tid < 128) sBst[tid - 64] = Bst[(size_t)t * 64 + tid - 64];
    __syncthreads();

    const float* Xin  = Xb + cur * (64 * 68);
    float*       Xout = Xb + (cur ^ 1) * (64 * 68);

    u64 a0 = 0, a1 = 0, a2 = 0, a3 = 0;
#pragma unroll 4
    for (int k = 0; k < klen; ++k){
      float4 av = *(const float4*)(Atr + k * 68 + i0);   // warp broadcast
      u64 xv = *(const u64*)(Xin + k * 68 + c0);
      fma2(a0, dup2(av.x), xv);
      fma2(a1, dup2(av.y), xv);
      fma2(a2, dup2(av.z), xv);
      fma2(a3, dup2(av.w), xv);
    }
    {
      u64 ip = pk2(sInp[c0], sInp[c0 + 1]);
      fma2(a0, dup2(sBst[i0 + 0]), ip);
      fma2(a1, dup2(sBst[i0 + 1]), ip);
      fma2(a2, dup2(sBst[i0 + 2]), ip);
      fma2(a3, dup2(sBst[i0 + 3]), ip);
    }
    *(u64*)(Xout + (i0 + 0) * 68 + c0) = a0;
    *(u64*)(Xout + (i0 + 1) * 68 + c0) = a1;
    *(u64*)(Xout + (i0 + 2) * 68 + c0) = a2;
    *(u64*)(Xout + (i0 + 3) * 68 + c0) = a3;

    // stage for transposed, coalesced output write
    float lo, hi;
    unpk2(a0, lo, hi); Ost[(i0 + 0) * 65 + c0] = lo; Ost[(i0 + 0) * 65 + c0 + 1] = hi;
    unpk2(a1, lo, hi); Ost[(i0 + 1) * 65 + c0] = lo; Ost[(i0 + 1) * 65 + c0 + 1] = hi;
    unpk2(a2, lo, hi); Ost[(i0 + 2) * 65 + c0] = lo; Ost[(i0 + 2) * 65 + c0 + 1] = hi;
    unpk2(a3, lo, hi); Ost[(i0 + 3) * 65 + c0] = lo; Ost[(i0 + 3) * 65 + c0 + 1] = hi;
    __syncthreads();

    float* op = out + (size_t)t * 4096;
    for (int idx = tid; idx < 4096; idx += 512){
      int b = idx >> 6, n = idx & 63;
      op[idx] = Ost[n * 65 + b];   // out[t][b][n] = X[n][b]
    }
    cur ^= 1;
  }
}

// ================= host =================
extern "C" void kernel_launch(void* const* d_in, const int* in_sizes, int n_in,
                              void* d_out, int out_size){
  const float* inp = (const float*)d_in[0];   // (L, B)
  const float* A   = (const float*)d_in[1];   // (L, N, N)
  const float* Bst = (const float*)d_in[2];   // (L, N)
  float* out = (float*)d_out;                 // (L, B, N)

  const int SMEM1 = (64 * 68 + 2 * 64 * 132 + 128) * 4;          // 85504
  const int SMEMS = (64 * 68 + 64 * 132 + 64 * 68) * 4;          // 68608
  const int SMEM3 = (64 * 68 + 2 * 64 * 68 + 64 * 65 + 128) * 4; // 69376

  cudaFuncSetAttribute(pass1_kernel, cudaFuncAttributeMaxDynamicSharedMemorySize, SMEM1);
  cudaFuncSetAttribute(scan_kernel,  cudaFuncAttributeMaxDynamicSharedMemorySize, SMEMS);
  cudaFuncSetAttribute(pass3_kernel, cudaFuncAttributeMaxDynamicSharedMemorySize, SMEM3);

  prep_kernel<<<L_TOT, 256>>>(A);
  pass1_kernel<<<NCH, 512, SMEM1>>>(inp, Bst);
  int src_w0 = 1;
  for (int d = 1; d < NCH; d <<= 1){
    scan_kernel<<<NCH, 512, SMEMS>>>(d, src_w0);
    src_w0 ^= 1;
  }
  // 7 rounds starting in g_W0 -> final scanned maps live in g_W1
  pass3_kernel<<<NCH, 512, SMEM3>>>(inp, Bst, out);
}

// round 5
// speedup vs baseline: 1.1917x; 1.1917x over previous
#include <cuda_runtime.h>
#include <cstdint>
#include <cstddef>

typedef unsigned long long u64;

#define L_TOT 4096
#define NN    64
#define TCH   32
#define NCH   128

// ---------------- scratch (device globals; no runtime allocation) ----------------
__device__ __align__(256) float g_At[L_TOT * NN * NN];     // g_At[t*4096 + k*64 + i] = A[t][i][k]
__device__ __align__(256) float g_S[8][NCH * NN * 128];    // scan round buffers [Y|M]
__device__ u64 g_flag[NCH];                                // per-block round-completion flags
__device__ u64 g_gen;                                      // launch generation (monotonic)

// warp -> row-tile permutation; per-SMSP sums of ti are all 30 (balanced triangular work)
__constant__ int TI_TAB[16] = {0,1,2,3, 5,4,7,6, 10,11,8,9, 15,14,13,12};

// ---------------- f32x2 helpers ----------------
__device__ __forceinline__ u64 pk2(float lo, float hi){
  u64 r; asm("mov.b64 %0, {%1,%2};" : "=l"(r) : "f"(lo), "f"(hi)); return r;
}
__device__ __forceinline__ u64 dup2(float v){
  u64 r; asm("mov.b64 %0, {%1,%1};" : "=l"(r) : "f"(v)); return r;
}
__device__ __forceinline__ void fma2(u64 &d, u64 a, u64 b){
  asm("fma.rn.f32x2 %0, %1, %2, %0;" : "+l"(d) : "l"(a), "l"(b));
}
__device__ __forceinline__ void add2(u64 &d, u64 a){
  asm("add.rn.f32x2 %0, %0, %1;" : "+l"(d) : "l"(a));
}
__device__ __forceinline__ void unpk2(u64 v, float &lo, float &hi){
  asm("mov.b64 {%0,%1}, %2;" : "=f"(lo), "=f"(hi) : "l"(v));
}

// ================= prep: transpose every A[t] (64x64) into g_At =================
__global__ void prep_kernel(const float* __restrict__ A){
  __shared__ float s[64 * 65];
  const int t = blockIdx.x;
  const float* src = A + (size_t)t * 4096;
  float* dst = g_At + (size_t)t * 4096;
  for (int idx = threadIdx.x; idx < 1024; idx += 256){
    int i = idx >> 4, k0 = (idx & 15) << 2;
    float4 v = *(const float4*)(src + i * 64 + k0);
    float* p = s + i * 65 + k0;
    p[0] = v.x; p[1] = v.y; p[2] = v.z; p[3] = v.w;
  }
  __syncthreads();
  for (int idx = threadIdx.x; idx < 1024; idx += 256){
    int k = idx >> 4, i0 = (idx & 15) << 2;
    float4 v;
    v.x = s[(i0 + 0) * 65 + k];
    v.y = s[(i0 + 1) * 65 + k];
    v.z = s[(i0 + 2) * 65 + k];
    v.w = s[(i0 + 3) * 65 + k];
    *(float4*)(dst + k * 64 + i0) = v;
  }
}

// ================= pass1: per-chunk affine map W = [Y | M] =================
__global__ void __launch_bounds__(512, 1)
pass1_kernel(const float* __restrict__ inp, const float* __restrict__ Bst){
  extern __shared__ float sm[];
  float* Atr  = sm;                    // [64][68]  Atr[k*68+i] = A[t][i][k]
  float* Wb   = Atr + 64 * 68;         // [2][64][132]
  float* sInp = Wb + 2 * 64 * 132;     // [64]
  float* sBst = sInp + 64;             // [64]

  const int c = blockIdx.x, tid = threadIdx.x;
  const int w = tid >> 5, lane = tid & 31;
  const int ti = TI_TAB[w], i0 = ti << 2, klen = i0 + 4, c0 = lane << 2;

  // this thread's two A-tile float4 slots (1024 slots total)
  const int k0s = tid >> 4,          j0s = (tid & 15) << 2;
  const int k1s = (tid + 512) >> 4,  j1s = ((tid + 512) & 15) << 2;

  for (int idx = tid; idx < 2 * 64 * 132; idx += 512) Wb[idx] = 0.0f;
  __syncthreads();
  if (tid < 64) Wb[tid * 132 + 64 + tid] = 1.0f;   // M = I in buffer 0

  const int t0 = c * TCH;
  // prefetch step 0
  const float* Ap = g_At + (size_t)t0 * 4096;
  float4 pA0 = *(const float4*)(Ap + k0s * 64 + j0s);
  float4 pA1 = *(const float4*)(Ap + k1s * 64 + j1s);
  float pIB = 0.0f;
  if (tid < 64)        pIB = inp[(size_t)t0 * 64 + tid];
  else if (tid < 128)  pIB = Bst[(size_t)t0 * 64 + (tid - 64)];

  int cur = 0;
  for (int s = 0; s < TCH; ++s){
    __syncthreads();   // previous compute done -> Atr reusable
    *(float4*)(Atr + k0s * 68 + j0s) = pA0;
    *(float4*)(Atr + k1s * 68 + j1s) = pA1;
    if (tid < 64)       sInp[tid]      = pIB;
    else if (tid < 128) sBst[tid - 64] = pIB;
    if (s + 1 < TCH){   // prefetch next step (overlaps compute below)
      const float* An = g_At + (size_t)(t0 + s + 1) * 4096;
      pA0 = *(const float4*)(An + k0s * 64 + j0s);
      pA1 = *(const float4*)(An + k1s * 64 + j1s);
      if (tid < 64)       pIB = inp[(size_t)(t0 + s + 1) * 64 + tid];
      else if (tid < 128) pIB = Bst[(size_t)(t0 + s + 1) * 64 + (tid - 64)];
    }
    __syncthreads();

    const float* Win  = Wb + cur * (64 * 132);
    float*       Wout = Wb + (cur ^ 1) * (64 * 132);

    u64 a00 = 0, a01 = 0, a10 = 0, a11 = 0, a20 = 0, a21 = 0, a30 = 0, a31 = 0;
#pragma unroll 4
    for (int k = 0; k < klen; ++k){
      float4 av = *(const float4*)(Atr + k * 68 + i0);   // warp broadcast
      u64 b0 = dup2(av.x), b1 = dup2(av.y), b2 = dup2(av.z), b3 = dup2(av.w);
      ulonglong2 wv = *(const ulonglong2*)(Win + k * 132 + c0);
      fma2(a00, b0, wv.x); fma2(a01, b0, wv.y);
      fma2(a10, b1, wv.x); fma2(a11, b1, wv.y);
      fma2(a20, b2, wv.x); fma2(a21, b2, wv.y);
      fma2(a30, b3, wv.x); fma2(a31, b3, wv.y);
    }

    if (c0 < 64){   // rank-1 input injection on the Y half
      u64 ipa = pk2(sInp[c0],     sInp[c0 + 1]);
      u64 ipb = pk2(sInp[c0 + 2], sInp[c0 + 3]);
      u64 q;
      q = dup2(sBst[i0 + 0]); fma2(a00, q, ipa); fma2(a01, q, ipb);
      q = dup2(sBst[i0 + 1]); fma2(a10, q, ipa); fma2(a11, q, ipb);
      q = dup2(sBst[i0 + 2]); fma2(a20, q, ipa); fma2(a21, q, ipb);
      q = dup2(sBst[i0 + 3]); fma2(a30, q, ipa); fma2(a31, q, ipb);
    }

    ulonglong2 v;
    v.x = a00; v.y = a01; *(ulonglong2*)(Wout + (i0 + 0) * 132 + c0) = v;
    v.x = a10; v.y = a11; *(ulonglong2*)(Wout + (i0 + 1) * 132 + c0) = v;
    v.x = a20; v.y = a21; *(ulonglong2*)(Wout + (i0 + 2) * 132 + c0) = v;
    v.x = a30; v.y = a31; *(ulonglong2*)(Wout + (i0 + 3) * 132 + c0) = v;
    cur ^= 1;
  }

  __syncthreads();
  const float* Wf = Wb + cur * (64 * 132);
  float* dst = g_S[0] + (size_t)c * 8192;
  for (int idx = tid; idx < 2048; idx += 512){
    int n = idx >> 5, q = (idx & 31) << 2;
    *(float4*)(dst + n * 128 + q) = *(const float4*)(Wf + n * 132 + q);
  }
}

// ================= scan_all: all 7 Kogge-Stone rounds in ONE launch =================
// 128 blocks <= 148 SMs -> all wave-1 resident; inter-block sync via monotonic flags.
__global__ void __launch_bounds__(512, 1)
scan_all_kernel(){
  extern __shared__ float sm[];
  float* Mtr  = sm;                 // [64][68]  Mtr[k*68+i] = M_later[i][k]
  float* Wbuf = Mtr + 64 * 68;      // [64][132] earlier [Y1|M1]
  float* Y2   = Wbuf + 64 * 132;    // [64][68]  later Y

  const int c = blockIdx.x, tid = threadIdx.x;
  const int w = tid >> 5, lane = tid & 31;
  const int ti = TI_TAB[w], i0 = ti << 2, klen = i0 + 4, c0 = lane << 2;
  const u64 gen8 = (*(volatile u64*)&g_gen) * 8ULL;

  for (int r = 1; r <= 7; ++r){
    const int d = 1 << (r - 1);
    const float* src = g_S[r - 1];
    float*       dst = g_S[r];

    if (c < d){
      // element already complete: copy forward
      const float* s = src + (size_t)c * 8192;
      float*       o = dst + (size_t)c * 8192;
      for (int idx = tid; idx < 2048; idx += 512)
        *(float4*)(o + idx * 4) = *(const float4*)(s + idx * 4);
    } else {
      if (r > 1){     // wait for producer block c-d to finish round r-1
        if (tid == 0){
          const u64 target = gen8 + (u64)(r - 1);
          while (*(volatile u64*)&g_flag[c - d] < target) { }
        }
      }
      __syncthreads();
      __threadfence();

      const float* later   = src + (size_t)c * 8192;        // own prev output (no wait)
      const float* earlier = src + (size_t)(c - d) * 8192;

      for (int idx = tid; idx < 4096; idx += 512){
        int i = idx >> 6, k = idx & 63;
        Mtr[k * 68 + i] = later[i * 128 + 64 + k];
      }
      for (int idx = tid; idx < 1024; idx += 512){
        int i = idx >> 4, q = (idx & 15) << 2;
        *(float4*)(Y2 + i * 68 + q) = *(const float4*)(later + i * 128 + q);
      }
      for (int idx = tid; idx < 2048; idx += 512){
        int n = idx >> 5, q = (idx & 31) << 2;
        *(float4*)(Wbuf + n * 132 + q) = *(const float4*)(earlier + n * 128 + q);
      }
      __syncthreads();

      u64 a00 = 0, a01 = 0, a10 = 0, a11 = 0, a20 = 0, a21 = 0, a30 = 0, a31 = 0;
#pragma unroll 4
      for (int k = 0; k < klen; ++k){
        float4 av = *(const float4*)(Mtr + k * 68 + i0);
        u64 b0 = dup2(av.x), b1 = dup2(av.y), b2 = dup2(av.z), b3 = dup2(av.w);
        ulonglong2 wv = *(const ulonglong2*)(Wbuf + k * 132 + c0);
        fma2(a00, b0, wv.x); fma2(a01, b0, wv.y);
        fma2(a10, b1, wv.x); fma2(a11, b1, wv.y);
        fma2(a20, b2, wv.x); fma2(a21, b2, wv.y);
        fma2(a30, b3, wv.x); fma2(a31, b3, wv.y);
      }

      if (c0 < 64){
        ulonglong2 yv;
        yv = *(const ulonglong2*)(Y2 + (i0 + 0) * 68 + c0); add2(a00, yv.x); add2(a01, yv.y);
        yv = *(const ulonglong2*)(Y2 + (i0 + 1) * 68 + c0); add2(a10, yv.x); add2(a11, yv.y);
        yv = *(const ulonglong2*)(Y2 + (i0 + 2) * 68 + c0); add2(a20, yv.x); add2(a21, yv.y);
        yv = *(const ulonglong2*)(Y2 + (i0 + 3) * 68 + c0); add2(a30, yv.x); add2(a31, yv.y);
      }

      float* o = dst + (size_t)c * 8192;
      ulonglong2 v;
      v.x = a00; v.y = a01; *(ulonglong2*)(o + (i0 + 0) * 128 + c0) = v;
      v.x = a10; v.y = a11; *(ulonglong2*)(o + (i0 + 1) * 128 + c0) = v;
      v.x = a20; v.y = a21; *(ulonglong2*)(o + (i0 + 2) * 128 + c0) = v;
      v.x = a30; v.y = a31; *(ulonglong2*)(o + (i0 + 3) * 128 + c0) = v;
    }

    // publish round-r completion
    __threadfence();
    __syncthreads();
    if (tid == 0) *(volatile u64*)&g_flag[c] = gen8 + (u64)r;
  }
}

__global__ void bump_gen_kernel(){ g_gen += 1ULL; }

// ================= pass3: re-run recurrence with carries, write out =================
__global__ void __launch_bounds__(512, 1)
pass3_kernel(const float* __restrict__ inp, const float* __restrict__ Bst,
             float* __restrict__ out){
  extern __shared__ float sm[];
  float* Atr  = sm;                    // [64][68]
  float* Xb   = Atr + 64 * 68;         // [2][64][68]   state X[n][b]
  float* Ost  = Xb + 2 * 64 * 68;      // [64][65]      output transpose stage
  float* sInp = Ost + 64 * 65;         // [64]
  float* sBst = sInp + 64;             // [64]

  const int c = blockIdx.x, tid = threadIdx.x;
  const int w = tid >> 5, lane = tid & 31;
  const int ti = TI_TAB[w], i0 = ti << 2, klen = i0 + 4, c0 = lane << 1;

  const int k0s = tid >> 4,          j0s = (tid & 15) << 2;
  const int k1s = (tid + 512) >> 4,  j1s = ((tid + 512) & 15) << 2;

  // init X = Y of scanned prefix (chunk c-1), or 0 for chunk 0
  if (c == 0){
    for (int idx = tid; idx < 64 * 68; idx += 512) Xb[idx] = 0.0f;
  } else {
    const float* Yp = g_S[7] + (size_t)(c - 1) * 8192;
    for (int idx = tid; idx < 1024; idx += 512){
      int n = idx >> 4, q = (idx & 15) << 2;
      *(float4*)(Xb + n * 68 + q) = *(const float4*)(Yp + n * 128 + q);
    }
  }

  const int t0 = c * TCH;
  const float* Ap = g_At + (size_t)t0 * 4096;
  float4 pA0 = *(const float4*)(Ap + k0s * 64 + j0s);
  float4 pA1 = *(const float4*)(Ap + k1s * 64 + j1s);
  float pIB = 0.0f;
  if (tid < 64)        pIB = inp[(size_t)t0 * 64 + tid];
  else if (tid < 128)  pIB = Bst[(size_t)t0 * 64 + (tid - 64)];

  int cur = 0;
  for (int s = 0; s < TCH; ++s){
    __syncthreads();    // prev out-write done reading Ost; prev compute done
    *(float4*)(Atr + k0s * 68 + j0s) = pA0;
    *(float4*)(Atr + k1s * 68 + j1s) = pA1;
    if (tid < 64)       sInp[tid]      = pIB;
    else if (tid < 128) sBst[tid - 64] = pIB;
    if (s + 1 < TCH){
      const float* An = g_At + (size_t)(t0 + s + 1) * 4096;
      pA0 = *(const float4*)(An + k0s * 64 + j0s);
      pA1 = *(const float4*)(An + k1s * 64 + j1s);
      if (tid < 64)       pIB = inp[(size_t)(t0 + s + 1) * 64 + tid];
      else if (tid < 128) pIB = Bst[(size_t)(t0 + s + 1) * 64 + (tid - 64)];
    }
    __syncthreads();

    const float* Xin  = Xb + cur * (64 * 68);
    float*       Xout = Xb + (cur ^ 1) * (64 * 68);

    u64 a0 = 0, a1 = 0, a2 = 0, a3 = 0;
#pragma unroll 4
    for (int k = 0; k < klen; ++k){
      float4 av = *(const float4*)(Atr + k * 68 + i0);   // warp broadcast
      u64 xv = *(const u64*)(Xin + k * 68 + c0);
      fma2(a0, dup2(av.x), xv);
      fma2(a1, dup2(av.y), xv);
      fma2(a2, dup2(av.z), xv);
      fma2(a3, dup2(av.w), xv);
    }
    {
      u64 ip = pk2(sInp[c0], sInp[c0 + 1]);
      fma2(a0, dup2(sBst[i0 + 0]), ip);
      fma2(a1, dup2(sBst[i0 + 1]), ip);
      fma2(a2, dup2(sBst[i0 + 2]), ip);
      fma2(a3, dup2(sBst[i0 + 3]), ip);
    }
    *(u64*)(Xout + (i0 + 0) * 68 + c0) = a0;
    *(u64*)(Xout + (i0 + 1) * 68 + c0) = a1;
    *(u64*)(Xout + (i0 + 2) * 68 + c0) = a2;
    *(u64*)(Xout + (i0 + 3) * 68 + c0) = a3;

    // stage for transposed, coalesced output write
    float lo, hi;
    unpk2(a0, lo, hi); Ost[(i0 + 0) * 65 + c0] = lo; Ost[(i0 + 0) * 65 + c0 + 1] = hi;
    unpk2(a1, lo, hi); Ost[(i0 + 1) * 65 + c0] = lo; Ost[(i0 + 1) * 65 + c0 + 1] = hi;
    unpk2(a2, lo, hi); Ost[(i0 + 2) * 65 + c0] = lo; Ost[(i0 + 2) * 65 + c0 + 1] = hi;
    unpk2(a3, lo, hi); Ost[(i0 + 3) * 65 + c0] = lo; Ost[(i0 + 3) * 65 + c0 + 1] = hi;
    __syncthreads();

    float* op = out + (size_t)(t0 + s) * 4096;
    for (int idx = tid; idx < 4096; idx += 512){
      int b = idx >> 6, n = idx & 63;
      op[idx] = Ost[n * 65 + b];   // out[t][b][n] = X[n][b]
    }
    cur ^= 1;
  }
}

// ================= host =================
extern "C" void kernel_launch(void* const* d_in, const int* in_sizes, int n_in,
                              void* d_out, int out_size){
  const float* inp = (const float*)d_in[0];   // (L, B)
  const float* A   = (const float*)d_in[1];   // (L, N, N)
  const float* Bst = (const float*)d_in[2];   // (L, N)
  float* out = (float*)d_out;                 // (L, B, N)

  const int SMEM1 = (64 * 68 + 2 * 64 * 132 + 128) * 4;          // 85504
  const int SMEMS = (64 * 68 + 64 * 132 + 64 * 68) * 4;          // 68608
  const int SMEM3 = (64 * 68 + 2 * 64 * 68 + 64 * 65 + 128) * 4; // 69376

  cudaFuncSetAttribute(pass1_kernel,    cudaFuncAttributeMaxDynamicSharedMemorySize, SMEM1);
  cudaFuncSetAttribute(scan_all_kernel, cudaFuncAttributeMaxDynamicSharedMemorySize, SMEMS);
  cudaFuncSetAttribute(pass3_kernel,    cudaFuncAttributeMaxDynamicSharedMemorySize, SMEM3);

  prep_kernel<<<L_TOT, 256>>>(A);
  pass1_kernel<<<NCH, 512, SMEM1>>>(inp, Bst);
  scan_all_kernel<<<NCH, 512, SMEMS>>>();
  pass3_kernel<<<NCH, 512, SMEM3>>>(inp, Bst, out);
  bump_gen_kernel<<<1, 1>>>();
}

// round 6
// speedup vs baseline: 1.2993x; 1.0903x over previous
#include <cuda_runtime.h>
#include <cstdint>
#include <cstddef>

typedef unsigned long long u64;

#define L_TOT 4096
#define NN    64
#define TCH   16
#define NCH   256

// ---------------- scratch (device globals; no runtime allocation) ----------------
__device__ __align__(256) float g_At[L_TOT * NN * NN];     // g_At[t*4096 + k*64 + i] = A[t][i][k]
__device__ __align__(256) float g_S[9][NCH * NN * 128];    // scan round buffers [Y|M]
__device__ u64 g_flag[NCH];                                // per-block round-completion flags
__device__ u64 g_gen;                                      // launch generation (monotonic)

// warp -> row-tile permutation (8 warps, 8-row tiles); per-SMSP klen sums all 72
__constant__ int TI_TAB[8] = {0,1,2,3, 7,6,5,4};

// ---------------- f32x2 helpers ----------------
__device__ __forceinline__ u64 pk2(float lo, float hi){
  u64 r; asm("mov.b64 %0, {%1,%2};" : "=l"(r) : "f"(lo), "f"(hi)); return r;
}
__device__ __forceinline__ u64 dup2(float v){
  u64 r; asm("mov.b64 %0, {%1,%1};" : "=l"(r) : "f"(v)); return r;
}
__device__ __forceinline__ void fma2(u64 &d, u64 a, u64 b){
  asm("fma.rn.f32x2 %0, %1, %2, %0;" : "+l"(d) : "l"(a), "l"(b));
}
__device__ __forceinline__ void add2(u64 &d, u64 a){
  asm("add.rn.f32x2 %0, %0, %1;" : "+l"(d) : "l"(a));
}
__device__ __forceinline__ void unpk2(u64 v, float &lo, float &hi){
  asm("mov.b64 {%0,%1}, %2;" : "=f"(lo), "=f"(hi) : "l"(v));
}

// ================= prep: transpose every A[t] (64x64) into g_At =================
__global__ void prep_kernel(const float* __restrict__ A){
  __shared__ float s[64 * 65];
  const int t = blockIdx.x;
  const float* src = A + (size_t)t * 4096;
  float* dst = g_At + (size_t)t * 4096;
  for (int idx = threadIdx.x; idx < 1024; idx += 256){
    int i = idx >> 4, k0 = (idx & 15) << 2;
    float4 v = *(const float4*)(src + i * 64 + k0);
    float* p = s + i * 65 + k0;
    p[0] = v.x; p[1] = v.y; p[2] = v.z; p[3] = v.w;
  }
  __syncthreads();
  for (int idx = threadIdx.x; idx < 1024; idx += 256){
    int k = idx >> 4, i0 = (idx & 15) << 2;
    float4 v;
    v.x = s[(i0 + 0) * 65 + k];
    v.y = s[(i0 + 1) * 65 + k];
    v.z = s[(i0 + 2) * 65 + k];
    v.w = s[(i0 + 3) * 65 + k];
    *(float4*)(dst + k * 64 + i0) = v;
  }
}

// ================= pass1: per-chunk affine map W = [Y | M] =================
__global__ void __launch_bounds__(256, 2)
pass1_kernel(const float* __restrict__ inp, const float* __restrict__ Bst){
  extern __shared__ float sm[];
  float* Atr  = sm;                    // [64][68]  Atr[k*68+i] = A[t][i][k]
  float* Wb   = Atr + 64 * 68;         // [2][64][132]
  float* sInp = Wb + 2 * 64 * 132;     // [64]
  float* sBst = sInp + 64;             // [64]

  const int c = blockIdx.x, tid = threadIdx.x;
  const int w = tid >> 5, lane = tid & 31;
  const int ti = TI_TAB[w], i0 = ti << 3, klen = i0 + 8, c0 = lane << 2;

  // A-tile staging: 1024 float4 slots over 256 threads = 4 each
  int ks[4], js[4];
#pragma unroll
  for (int q = 0; q < 4; ++q){ int s = tid + q * 256; ks[q] = s >> 4; js[q] = (s & 15) << 2; }

  for (int idx = tid; idx < 2 * 64 * 132; idx += 256) Wb[idx] = 0.0f;
  __syncthreads();
  if (tid < 64) Wb[tid * 132 + 64 + tid] = 1.0f;   // M = I in buffer 0

  const int t0 = c * TCH;
  const float* Ap = g_At + (size_t)t0 * 4096;
  float4 pA[4];
#pragma unroll
  for (int q = 0; q < 4; ++q) pA[q] = *(const float4*)(Ap + ks[q] * 64 + js[q]);
  float pIB = 0.0f;
  if (tid < 64)       pIB = inp[(size_t)t0 * 64 + tid];
  else if (tid < 128) pIB = Bst[(size_t)t0 * 64 + (tid - 64)];

  int cur = 0;
  for (int s = 0; s < TCH; ++s){
    __syncthreads();
#pragma unroll
    for (int q = 0; q < 4; ++q) *(float4*)(Atr + ks[q] * 68 + js[q]) = pA[q];
    if (tid < 64)       sInp[tid]      = pIB;
    else if (tid < 128) sBst[tid - 64] = pIB;
    if (s + 1 < TCH){
      const float* An = g_At + (size_t)(t0 + s + 1) * 4096;
#pragma unroll
      for (int q = 0; q < 4; ++q) pA[q] = *(const float4*)(An + ks[q] * 64 + js[q]);
      if (tid < 64)       pIB = inp[(size_t)(t0 + s + 1) * 64 + tid];
      else if (tid < 128) pIB = Bst[(size_t)(t0 + s + 1) * 64 + (tid - 64)];
    }
    __syncthreads();

    const float* Win  = Wb + cur * (64 * 132);
    float*       Wout = Wb + (cur ^ 1) * (64 * 132);

    u64 acc[8][2];
#pragma unroll
    for (int r = 0; r < 8; ++r){ acc[r][0] = 0; acc[r][1] = 0; }

#pragma unroll 4
    for (int k = 0; k < klen; ++k){
      float4 av0 = *(const float4*)(Atr + k * 68 + i0);       // warp broadcast
      float4 av1 = *(const float4*)(Atr + k * 68 + i0 + 4);
      ulonglong2 wv = *(const ulonglong2*)(Win + k * 132 + c0);
      u64 b;
      b = dup2(av0.x); fma2(acc[0][0], b, wv.x); fma2(acc[0][1], b, wv.y);
      b = dup2(av0.y); fma2(acc[1][0], b, wv.x); fma2(acc[1][1], b, wv.y);
      b = dup2(av0.z); fma2(acc[2][0], b, wv.x); fma2(acc[2][1], b, wv.y);
      b = dup2(av0.w); fma2(acc[3][0], b, wv.x); fma2(acc[3][1], b, wv.y);
      b = dup2(av1.x); fma2(acc[4][0], b, wv.x); fma2(acc[4][1], b, wv.y);
      b = dup2(av1.y); fma2(acc[5][0], b, wv.x); fma2(acc[5][1], b, wv.y);
      b = dup2(av1.z); fma2(acc[6][0], b, wv.x); fma2(acc[6][1], b, wv.y);
      b = dup2(av1.w); fma2(acc[7][0], b, wv.x); fma2(acc[7][1], b, wv.y);
    }

    if (c0 < 64){   // rank-1 input injection on the Y half
      u64 ipa = pk2(sInp[c0],     sInp[c0 + 1]);
      u64 ipb = pk2(sInp[c0 + 2], sInp[c0 + 3]);
#pragma unroll
      for (int r = 0; r < 8; ++r){
        u64 q = dup2(sBst[i0 + r]);
        fma2(acc[r][0], q, ipa); fma2(acc[r][1], q, ipb);
      }
    }

#pragma unroll
    for (int r = 0; r < 8; ++r){
      ulonglong2 v; v.x = acc[r][0]; v.y = acc[r][1];
      *(ulonglong2*)(Wout + (i0 + r) * 132 + c0) = v;
    }
    cur ^= 1;
  }

  __syncthreads();
  const float* Wf = Wb + cur * (64 * 132);
  float* dst = g_S[0] + (size_t)c * 8192;
  for (int idx = tid; idx < 2048; idx += 256){
    int n = idx >> 5, q = (idx & 31) << 2;
    *(float4*)(dst + n * 128 + q) = *(const float4*)(Wf + n * 132 + q);
  }
}

// ================= scan_all: all 8 Kogge-Stone rounds in ONE launch =================
// 256 blocks, 3 CTAs/SM possible (smem 68.6KB) -> all wave-1 resident; flag sync.
__global__ void __launch_bounds__(256, 2)
scan_all_kernel(){
  extern __shared__ float sm[];
  float* Mtr  = sm;                 // [64][68]  Mtr[k*68+i] = M_later[i][k]
  float* Wbuf = Mtr + 64 * 68;      // [64][132] earlier [Y1|M1]
  float* Y2   = Wbuf + 64 * 132;    // [64][68]  later Y

  const int c = blockIdx.x, tid = threadIdx.x;
  const int w = tid >> 5, lane = tid & 31;
  const int ti = TI_TAB[w], i0 = ti << 3, klen = i0 + 8, c0 = lane << 2;
  const u64 gen = (*(volatile u64*)&g_gen) * 9ULL;

  for (int r = 1; r <= 8; ++r){
    const int d = 1 << (r - 1);
    const float* src = g_S[r - 1];
    float*       dst = g_S[r];

    if (c < d){
      const float* s = src + (size_t)c * 8192;
      float*       o = dst + (size_t)c * 8192;
      for (int idx = tid; idx < 2048; idx += 256)
        *(float4*)(o + idx * 4) = *(const float4*)(s + idx * 4);
    } else {
      if (r > 1){
        if (tid == 0){
          const u64 target = gen + (u64)(r - 1);
          while (*(volatile u64*)&g_flag[c - d] < target) { }
        }
      }
      __syncthreads();
      __threadfence();

      const float* later   = src + (size_t)c * 8192;
      const float* earlier = src + (size_t)(c - d) * 8192;

      for (int idx = tid; idx < 4096; idx += 256){
        int i = idx >> 6, k = idx & 63;
        Mtr[k * 68 + i] = later[i * 128 + 64 + k];
      }
      for (int idx = tid; idx < 1024; idx += 256){
        int i = idx >> 4, q = (idx & 15) << 2;
        *(float4*)(Y2 + i * 68 + q) = *(const float4*)(later + i * 128 + q);
      }
      for (int idx = tid; idx < 2048; idx += 256){
        int n = idx >> 5, q = (idx & 31) << 2;
        *(float4*)(Wbuf + n * 132 + q) = *(const float4*)(earlier + n * 128 + q);
      }
      __syncthreads();

      u64 acc[8][2];
#pragma unroll
      for (int rr = 0; rr < 8; ++rr){ acc[rr][0] = 0; acc[rr][1] = 0; }

#pragma unroll 4
      for (int k = 0; k < klen; ++k){
        float4 av0 = *(const float4*)(Mtr + k * 68 + i0);
        float4 av1 = *(const float4*)(Mtr + k * 68 + i0 + 4);
        ulonglong2 wv = *(const ulonglong2*)(Wbuf + k * 132 + c0);
        u64 b;
        b = dup2(av0.x); fma2(acc[0][0], b, wv.x); fma2(acc[0][1], b, wv.y);
        b = dup2(av0.y); fma2(acc[1][0], b, wv.x); fma2(acc[1][1], b, wv.y);
        b = dup2(av0.z); fma2(acc[2][0], b, wv.x); fma2(acc[2][1], b, wv.y);
        b = dup2(av0.w); fma2(acc[3][0], b, wv.x); fma2(acc[3][1], b, wv.y);
        b = dup2(av1.x); fma2(acc[4][0], b, wv.x); fma2(acc[4][1], b, wv.y);
        b = dup2(av1.y); fma2(acc[5][0], b, wv.x); fma2(acc[5][1], b, wv.y);
        b = dup2(av1.z); fma2(acc[6][0], b, wv.x); fma2(acc[6][1], b, wv.y);
        b = dup2(av1.w); fma2(acc[7][0], b, wv.x); fma2(acc[7][1], b, wv.y);
      }

      if (c0 < 64){
#pragma unroll
        for (int rr = 0; rr < 8; ++rr){
          ulonglong2 yv = *(const ulonglong2*)(Y2 + (i0 + rr) * 68 + c0);
          add2(acc[rr][0], yv.x); add2(acc[rr][1], yv.y);
        }
      }

      float* o = dst + (size_t)c * 8192;
#pragma unroll
      for (int rr = 0; rr < 8; ++rr){
        ulonglong2 v; v.x = acc[rr][0]; v.y = acc[rr][1];
        *(ulonglong2*)(o + (i0 + rr) * 128 + c0) = v;
      }
    }

    __threadfence();
    __syncthreads();
    if (tid == 0) *(volatile u64*)&g_flag[c] = gen + (u64)r;
  }
}

__global__ void bump_gen_kernel(){ g_gen += 1ULL; }

// ================= pass3: re-run recurrence with carries, write out =================
__global__ void __launch_bounds__(256, 2)
pass3_kernel(const float* __restrict__ inp, const float* __restrict__ Bst,
             float* __restrict__ out){
  extern __shared__ float sm[];
  float* Atr  = sm;                    // [64][68]
  float* Xb   = Atr + 64 * 68;         // [2][64][68]   state X[n][b]
  float* sInp = Xb + 2 * 64 * 68;      // [64]
  float* sBst = sInp + 64;             // [64]

  const int c = blockIdx.x, tid = threadIdx.x;
  const int w = tid >> 5, lane = tid & 31;
  const int ti = TI_TAB[w], i0 = ti << 3, klen = i0 + 8, c0 = lane << 1;

  int ks[4], js[4];
#pragma unroll
  for (int q = 0; q < 4; ++q){ int s = tid + q * 256; ks[q] = s >> 4; js[q] = (s & 15) << 2; }

  // init X = Y of scanned prefix (chunk c-1), or 0 for chunk 0
  if (c == 0){
    for (int idx = tid; idx < 64 * 68; idx += 256) Xb[idx] = 0.0f;
  } else {
    const float* Yp = g_S[8] + (size_t)(c - 1) * 8192;
    for (int idx = tid; idx < 1024; idx += 256){
      int n = idx >> 4, q = (idx & 15) << 2;
      *(float4*)(Xb + n * 68 + q) = *(const float4*)(Yp + n * 128 + q);
    }
  }

  const int t0 = c * TCH;
  const float* Ap = g_At + (size_t)t0 * 4096;
  float4 pA[4];
#pragma unroll
  for (int q = 0; q < 4; ++q) pA[q] = *(const float4*)(Ap + ks[q] * 64 + js[q]);
  float pIB = 0.0f;
  if (tid < 64)       pIB = inp[(size_t)t0 * 64 + tid];
  else if (tid < 128) pIB = Bst[(size_t)t0 * 64 + (tid - 64)];

  int cur = 0;
  for (int s = 0; s < TCH; ++s){
    __syncthreads();
#pragma unroll
    for (int q = 0; q < 4; ++q) *(float4*)(Atr + ks[q] * 68 + js[q]) = pA[q];
    if (tid < 64)       sInp[tid]      = pIB;
    else if (tid < 128) sBst[tid - 64] = pIB;
    if (s + 1 < TCH){
      const float* An = g_At + (size_t)(t0 + s + 1) * 4096;
#pragma unroll
      for (int q = 0; q < 4; ++q) pA[q] = *(const float4*)(An + ks[q] * 64 + js[q]);
      if (tid < 64)       pIB = inp[(size_t)(t0 + s + 1) * 64 + tid];
      else if (tid < 128) pIB = Bst[(size_t)(t0 + s + 1) * 64 + (tid - 64)];
    }
    __syncthreads();

    const float* Xin  = Xb + cur * (64 * 68);
    float*       Xout = Xb + (cur ^ 1) * (64 * 68);

    u64 a[8];
#pragma unroll
    for (int r = 0; r < 8; ++r) a[r] = 0;

#pragma unroll 4
    for (int k = 0; k < klen; ++k){
      float4 av0 = *(const float4*)(Atr + k * 68 + i0);       // warp broadcast
      float4 av1 = *(const float4*)(Atr + k * 68 + i0 + 4);
      u64 xv = *(const u64*)(Xin + k * 68 + c0);
      fma2(a[0], dup2(av0.x), xv);
      fma2(a[1], dup2(av0.y), xv);
      fma2(a[2], dup2(av0.z), xv);
      fma2(a[3], dup2(av0.w), xv);
      fma2(a[4], dup2(av1.x), xv);
      fma2(a[5], dup2(av1.y), xv);
      fma2(a[6], dup2(av1.z), xv);
      fma2(a[7], dup2(av1.w), xv);
    }
    {
      u64 ip = pk2(sInp[c0], sInp[c0 + 1]);
#pragma unroll
      for (int r = 0; r < 8; ++r) fma2(a[r], dup2(sBst[i0 + r]), ip);
    }
#pragma unroll
    for (int r = 0; r < 8; ++r)
      *(u64*)(Xout + (i0 + r) * 68 + c0) = a[r];

    // direct register -> gmem output: out[t][b][n] = X[n][b]
    float lo[8], hi[8];
#pragma unroll
    for (int r = 0; r < 8; ++r) unpk2(a[r], lo[r], hi[r]);
    float* base = out + (size_t)(t0 + s) * 4096 + (size_t)c0 * 64 + i0;
    float4 v;
    v.x = lo[0]; v.y = lo[1]; v.z = lo[2]; v.w = lo[3]; *(float4*)(base)      = v;
    v.x = lo[4]; v.y = lo[5]; v.z = lo[6]; v.w = lo[7]; *(float4*)(base + 4)  = v;
    v.x = hi[0]; v.y = hi[1]; v.z = hi[2]; v.w = hi[3]; *(float4*)(base + 64) = v;
    v.x = hi[4]; v.y = hi[5]; v.z = hi[6]; v.w = hi[7]; *(float4*)(base + 68) = v;

    cur ^= 1;
  }
}

// ================= host =================
extern "C" void kernel_launch(void* const* d_in, const int* in_sizes, int n_in,
                              void* d_out, int out_size){
  const float* inp = (const float*)d_in[0];   // (L, B)
  const float* A   = (const float*)d_in[1];   // (L, N, N)
  const float* Bst = (const float*)d_in[2];   // (L, N)
  float* out = (float*)d_out;                 // (L, B, N)

  const int SMEM1 = (64 * 68 + 2 * 64 * 132 + 128) * 4;  // 85504
  const int SMEMS = (64 * 68 + 64 * 132 + 64 * 68) * 4;  // 68608
  const int SMEM3 = (64 * 68 + 2 * 64 * 68 + 128) * 4;   // 52736

  cudaFuncSetAttribute(pass1_kernel,    cudaFuncAttributeMaxDynamicSharedMemorySize, SMEM1);
  cudaFuncSetAttribute(scan_all_kernel, cudaFuncAttributeMaxDynamicSharedMemorySize, SMEMS);
  cudaFuncSetAttribute(pass3_kernel,    cudaFuncAttributeMaxDynamicSharedMemorySize, SMEM3);

  prep_kernel<<<L_TOT, 256>>>(A);
  pass1_kernel<<<NCH, 256, SMEM1>>>(inp, Bst);
  scan_all_kernel<<<NCH, 256, SMEMS>>>();
  pass3_kernel<<<NCH, 256, SMEM3>>>(inp, Bst, out);
  bump_gen_kernel<<<1, 1>>>();
}

// round 7
// speedup vs baseline: 1.3459x; 1.0359x over previous
#include <cuda_runtime.h>
#include <cstdint>
#include <cstddef>

typedef unsigned long long u64;

#define L_TOT 4096
#define NN    64
#define TCH   16
#define NCH   256

// ---------------- scratch (device globals; no runtime allocation) ----------------
__device__ __align__(256) float g_At[L_TOT * NN * NN];     // g_At[t*4096 + k*64 + i] = A[t][i][k]
__device__ __align__(256) float g_S[9][NCH * NN * 128];    // scan round buffers [Y|M]
__device__ u64 g_flag[NCH];                                // per-block round-completion flags
__device__ u64 g_gen;                                      // launch generation (monotonic)

// ---------------- f32x2 helpers ----------------
__device__ __forceinline__ u64 pk2(float lo, float hi){
  u64 r; asm("mov.b64 %0, {%1,%2};" : "=l"(r) : "f"(lo), "f"(hi)); return r;
}
__device__ __forceinline__ u64 dup2(float v){
  u64 r; asm("mov.b64 %0, {%1,%1};" : "=l"(r) : "f"(v)); return r;
}
__device__ __forceinline__ void fma2(u64 &d, u64 a, u64 b){
  asm("fma.rn.f32x2 %0, %1, %2, %0;" : "+l"(d) : "l"(a), "l"(b));
}
__device__ __forceinline__ void add2(u64 &d, u64 a){
  asm("add.rn.f32x2 %0, %0, %1;" : "+l"(d) : "l"(a));
}
__device__ __forceinline__ void unpk2(u64 v, float &lo, float &hi){
  asm("mov.b64 {%0,%1}, %2;" : "=f"(lo), "=f"(hi) : "l"(v));
}

// ================= prep: transpose every A[t] (64x64) into g_At =================
__global__ void prep_kernel(const float* __restrict__ A){
  __shared__ float s[64 * 65];
  const int t = blockIdx.x;
  const float* src = A + (size_t)t * 4096;
  float* dst = g_At + (size_t)t * 4096;
  for (int idx = threadIdx.x; idx < 1024; idx += 256){
    int i = idx >> 4, k0 = (idx & 15) << 2;
    float4 v = *(const float4*)(src + i * 64 + k0);
    float* p = s + i * 65 + k0;
    p[0] = v.x; p[1] = v.y; p[2] = v.z; p[3] = v.w;
  }
  __syncthreads();
  for (int idx = threadIdx.x; idx < 1024; idx += 256){
    int k = idx >> 4, i0 = (idx & 15) << 2;
    float4 v;
    v.x = s[(i0 + 0) * 65 + k];
    v.y = s[(i0 + 1) * 65 + k];
    v.z = s[(i0 + 2) * 65 + k];
    v.w = s[(i0 + 3) * 65 + k];
    *(float4*)(dst + k * 64 + i0) = v;
  }
}

// ================= pass1: per-chunk affine map W = [Y | M] =================
// Balanced rows: warp w owns rows [4w,4w+3] and [60-4w,63-4w]; equal work per warp.
// Single barrier per step: A tile + inp/B double-buffered in smem.
__global__ void __launch_bounds__(256, 2)
pass1_kernel(const float* __restrict__ inp, const float* __restrict__ Bst){
  extern __shared__ float sm[];
  float* Atr = sm;                     // [2][64][68]  Atr[b][k*68+i] = A[t][i][k]
  float* Wb  = Atr + 2 * 64 * 68;      // [2][64][132]
  float* sIB = Wb + 2 * 64 * 132;      // [2][128]  [0..63]=inp, [64..127]=B

  const int c = blockIdx.x, tid = threadIdx.x;
  const int w = tid >> 5, lane = tid & 31;
  const int lo0 = w << 2;              // low row group
  const int hi0 = 60 - (w << 2);       // high row group
  const int klo = lo0 + 4;             // k < klo: both groups
  const int khi = 64 - lo0;            // k < khi: high group
  const int c0  = lane << 2;

  // A-tile staging: 1024 float4 slots over 256 threads = 4 each
  int ks[4], js[4];
#pragma unroll
  for (int q = 0; q < 4; ++q){ int s = tid + q * 256; ks[q] = s >> 4; js[q] = (s & 15) << 2; }

  for (int idx = tid; idx < 2 * 64 * 132; idx += 256) Wb[idx] = 0.0f;
  __syncthreads();
  if (tid < 64) Wb[tid * 132 + 64 + tid] = 1.0f;   // M = I in buffer 0

  const int t0 = c * TCH;
  // load step 0 into smem buf 0
  {
    const float* Ap = g_At + (size_t)t0 * 4096;
#pragma unroll
    for (int q = 0; q < 4; ++q)
      *(float4*)(Atr + ks[q] * 68 + js[q]) = *(const float4*)(Ap + ks[q] * 64 + js[q]);
    if (tid < 64)       sIB[tid]      = inp[(size_t)t0 * 64 + tid];
    else if (tid < 128) sIB[tid]      = Bst[(size_t)t0 * 64 + (tid - 64)];
  }
  // prefetch step 1 into regs
  float4 pA[4]; float pIB = 0.0f;
  if (TCH > 1){
    const float* An = g_At + (size_t)(t0 + 1) * 4096;
#pragma unroll
    for (int q = 0; q < 4; ++q) pA[q] = *(const float4*)(An + ks[q] * 64 + js[q]);
    if (tid < 64)       pIB = inp[(size_t)(t0 + 1) * 64 + tid];
    else if (tid < 128) pIB = Bst[(size_t)(t0 + 1) * 64 + (tid - 64)];
  }
  __syncthreads();

  int cur = 0;
  for (int s = 0; s < TCH; ++s){
    const int ab = s & 1;
    const float* At  = Atr + ab * (64 * 68);
    const float* ib  = sIB + ab * 128;
    const float* Win = Wb + cur * (64 * 132);
    float*       Wout= Wb + (cur ^ 1) * (64 * 132);

    // stage step s+1 (regs -> smem alt buffer); prefetch step s+2 (gmem -> regs)
    if (s + 1 < TCH){
      float* Ad = Atr + (ab ^ 1) * (64 * 68);
#pragma unroll
      for (int q = 0; q < 4; ++q) *(float4*)(Ad + ks[q] * 68 + js[q]) = pA[q];
      if (tid < 128) sIB[(ab ^ 1) * 128 + tid] = pIB;
    }
    if (s + 2 < TCH){
      const float* An = g_At + (size_t)(t0 + s + 2) * 4096;
#pragma unroll
      for (int q = 0; q < 4; ++q) pA[q] = *(const float4*)(An + ks[q] * 64 + js[q]);
      if (tid < 64)       pIB = inp[(size_t)(t0 + s + 2) * 64 + tid];
      else if (tid < 128) pIB = Bst[(size_t)(t0 + s + 2) * 64 + (tid - 64)];
    }

    u64 accL[4][2], accH[4][2];
#pragma unroll
    for (int r = 0; r < 4; ++r){ accL[r][0]=0; accL[r][1]=0; accH[r][0]=0; accH[r][1]=0; }

#pragma unroll 4
    for (int k = 0; k < klo; ++k){
      float4 avL = *(const float4*)(At + k * 68 + lo0);
      float4 avH = *(const float4*)(At + k * 68 + hi0);
      ulonglong2 wv = *(const ulonglong2*)(Win + k * 132 + c0);
      u64 b;
      b = dup2(avL.x); fma2(accL[0][0], b, wv.x); fma2(accL[0][1], b, wv.y);
      b = dup2(avL.y); fma2(accL[1][0], b, wv.x); fma2(accL[1][1], b, wv.y);
      b = dup2(avL.z); fma2(accL[2][0], b, wv.x); fma2(accL[2][1], b, wv.y);
      b = dup2(avL.w); fma2(accL[3][0], b, wv.x); fma2(accL[3][1], b, wv.y);
      b = dup2(avH.x); fma2(accH[0][0], b, wv.x); fma2(accH[0][1], b, wv.y);
      b = dup2(avH.y); fma2(accH[1][0], b, wv.x); fma2(accH[1][1], b, wv.y);
      b = dup2(avH.z); fma2(accH[2][0], b, wv.x); fma2(accH[2][1], b, wv.y);
      b = dup2(avH.w); fma2(accH[3][0], b, wv.x); fma2(accH[3][1], b, wv.y);
    }
#pragma unroll 4
    for (int k = klo; k < khi; ++k){
      float4 avH = *(const float4*)(At + k * 68 + hi0);
      ulonglong2 wv = *(const ulonglong2*)(Win + k * 132 + c0);
      u64 b;
      b = dup2(avH.x); fma2(accH[0][0], b, wv.x); fma2(accH[0][1], b, wv.y);
      b = dup2(avH.y); fma2(accH[1][0], b, wv.x); fma2(accH[1][1], b, wv.y);
      b = dup2(avH.z); fma2(accH[2][0], b, wv.x); fma2(accH[2][1], b, wv.y);
      b = dup2(avH.w); fma2(accH[3][0], b, wv.x); fma2(accH[3][1], b, wv.y);
    }

    if (c0 < 64){   // rank-1 input injection on the Y half
      u64 ipa = pk2(ib[c0],     ib[c0 + 1]);
      u64 ipb = pk2(ib[c0 + 2], ib[c0 + 3]);
#pragma unroll
      for (int r = 0; r < 4; ++r){
        u64 q;
        q = dup2(ib[64 + lo0 + r]); fma2(accL[r][0], q, ipa); fma2(accL[r][1], q, ipb);
        q = dup2(ib[64 + hi0 + r]); fma2(accH[r][0], q, ipa); fma2(accH[r][1], q, ipb);
      }
    }

#pragma unroll
    for (int r = 0; r < 4; ++r){
      ulonglong2 v;
      v.x = accL[r][0]; v.y = accL[r][1]; *(ulonglong2*)(Wout + (lo0 + r) * 132 + c0) = v;
      v.x = accH[r][0]; v.y = accH[r][1]; *(ulonglong2*)(Wout + (hi0 + r) * 132 + c0) = v;
    }
    __syncthreads();
    cur ^= 1;
  }

  const float* Wf = Wb + cur * (64 * 132);
  float* dst = g_S[0] + (size_t)c * 8192;
  for (int idx = tid; idx < 2048; idx += 256){
    int n = idx >> 5, q = (idx & 31) << 2;
    *(float4*)(dst + n * 128 + q) = *(const float4*)(Wf + n * 132 + q);
  }
}

// ================= scan_all: all 8 Kogge-Stone rounds in ONE launch =================
__global__ void __launch_bounds__(256, 2)
scan_all_kernel(){
  extern __shared__ float sm[];
  float* Mtr  = sm;                 // [64][68]  Mtr[k*68+i] = M_later[i][k]
  float* Wbuf = Mtr + 64 * 68;      // [64][132] earlier [Y1|M1]
  float* Y2   = Wbuf + 64 * 132;    // [64][68]  later Y

  const int c = blockIdx.x, tid = threadIdx.x;
  const int w = tid >> 5, lane = tid & 31;
  const int lo0 = w << 2, hi0 = 60 - (w << 2);
  const int klo = lo0 + 4, khi = 64 - lo0;
  const int c0  = lane << 2;
  const u64 gen = (*(volatile u64*)&g_gen) * 9ULL;

  for (int r = 1; r <= 8; ++r){
    const int d = 1 << (r - 1);
    const float* src = g_S[r - 1];
    float*       dst = g_S[r];

    if (c < d){
      const float* s = src + (size_t)c * 8192;
      float*       o = dst + (size_t)c * 8192;
      for (int idx = tid; idx < 2048; idx += 256)
        *(float4*)(o + idx * 4) = *(const float4*)(s + idx * 4);
    } else {
      if (r > 1){
        if (tid == 0){
          const u64 target = gen + (u64)(r - 1);
          while (*(volatile u64*)&g_flag[c - d] < target) { }
        }
      }
      __syncthreads();
      __threadfence();

      const float* later   = src + (size_t)c * 8192;
      const float* earlier = src + (size_t)(c - d) * 8192;

      for (int idx = tid; idx < 4096; idx += 256){
        int i = idx >> 6, k = idx & 63;
        Mtr[k * 68 + i] = later[i * 128 + 64 + k];
      }
      for (int idx = tid; idx < 1024; idx += 256){
        int i = idx >> 4, q = (idx & 15) << 2;
        *(float4*)(Y2 + i * 68 + q) = *(const float4*)(later + i * 128 + q);
      }
      for (int idx = tid; idx < 2048; idx += 256){
        int n = idx >> 5, q = (idx & 31) << 2;
        *(float4*)(Wbuf + n * 132 + q) = *(const float4*)(earlier + n * 128 + q);
      }
      __syncthreads();

      u64 accL[4][2], accH[4][2];
#pragma unroll
      for (int rr = 0; rr < 4; ++rr){ accL[rr][0]=0; accL[rr][1]=0; accH[rr][0]=0; accH[rr][1]=0; }

#pragma unroll 4
      for (int k = 0; k < klo; ++k){
        float4 avL = *(const float4*)(Mtr + k * 68 + lo0);
        float4 avH = *(const float4*)(Mtr + k * 68 + hi0);
        ulonglong2 wv = *(const ulonglong2*)(Wbuf + k * 132 + c0);
        u64 b;
        b = dup2(avL.x); fma2(accL[0][0], b, wv.x); fma2(accL[0][1], b, wv.y);
        b = dup2(avL.y); fma2(accL[1][0], b, wv.x); fma2(accL[1][1], b, wv.y);
        b = dup2(avL.z); fma2(accL[2][0], b, wv.x); fma2(accL[2][1], b, wv.y);
        b = dup2(avL.w); fma2(accL[3][0], b, wv.x); fma2(accL[3][1], b, wv.y);
        b = dup2(avH.x); fma2(accH[0][0], b, wv.x); fma2(accH[0][1], b, wv.y);
        b = dup2(avH.y); fma2(accH[1][0], b, wv.x); fma2(accH[1][1], b, wv.y);
        b = dup2(avH.z); fma2(accH[2][0], b, wv.x); fma2(accH[2][1], b, wv.y);
        b = dup2(avH.w); fma2(accH[3][0], b, wv.x); fma2(accH[3][1], b, wv.y);
      }
#pragma unroll 4
      for (int k = klo; k < khi; ++k){
        float4 avH = *(const float4*)(Mtr + k * 68 + hi0);
        ulonglong2 wv = *(const ulonglong2*)(Wbuf + k * 132 + c0);
        u64 b;
        b = dup2(avH.x); fma2(accH[0][0], b, wv.x); fma2(accH[0][1], b, wv.y);
        b = dup2(avH.y); fma2(accH[1][0], b, wv.x); fma2(accH[1][1], b, wv.y);
        b = dup2(avH.z); fma2(accH[2][0], b, wv.x); fma2(accH[2][1], b, wv.y);
        b = dup2(avH.w); fma2(accH[3][0], b, wv.x); fma2(accH[3][1], b, wv.y);
      }

      if (c0 < 64){
#pragma unroll
        for (int rr = 0; rr < 4; ++rr){
          ulonglong2 yv;
          yv = *(const ulonglong2*)(Y2 + (lo0 + rr) * 68 + c0); add2(accL[rr][0], yv.x); add2(accL[rr][1], yv.y);
          yv = *(const ulonglong2*)(Y2 + (hi0 + rr) * 68 + c0); add2(accH[rr][0], yv.x); add2(accH[rr][1], yv.y);
        }
      }

      float* o = dst + (size_t)c * 8192;
#pragma unroll
      for (int rr = 0; rr < 4; ++rr){
        ulonglong2 v;
        v.x = accL[rr][0]; v.y = accL[rr][1]; *(ulonglong2*)(o + (lo0 + rr) * 128 + c0) = v;
        v.x = accH[rr][0]; v.y = accH[rr][1]; *(ulonglong2*)(o + (hi0 + rr) * 128 + c0) = v;
      }
    }

    __threadfence();
    __syncthreads();
    if (tid == 0) *(volatile u64*)&g_flag[c] = gen + (u64)r;
  }
}

__global__ void bump_gen_kernel(){ g_gen += 1ULL; }

// ================= pass3: re-run recurrence with carries, write out =================
__global__ void __launch_bounds__(256, 2)
pass3_kernel(const float* __restrict__ inp, const float* __restrict__ Bst,
             float* __restrict__ out){
  extern __shared__ float sm[];
  float* Atr = sm;                     // [2][64][68]
  float* Xb  = Atr + 2 * 64 * 68;      // [2][64][68]   state X[n][b]
  float* sIB = Xb + 2 * 64 * 68;       // [2][128]

  const int c = blockIdx.x, tid = threadIdx.x;
  const int w = tid >> 5, lane = tid & 31;
  const int lo0 = w << 2, hi0 = 60 - (w << 2);
  const int klo = lo0 + 4, khi = 64 - lo0;
  const int c0  = lane << 1;

  int ks[4], js[4];
#pragma unroll
  for (int q = 0; q < 4; ++q){ int s = tid + q * 256; ks[q] = s >> 4; js[q] = (s & 15) << 2; }

  // init X = Y of scanned prefix (chunk c-1), or 0 for chunk 0
  if (c == 0){
    for (int idx = tid; idx < 64 * 68; idx += 256) Xb[idx] = 0.0f;
  } else {
    const float* Yp = g_S[8] + (size_t)(c - 1) * 8192;
    for (int idx = tid; idx < 1024; idx += 256){
      int n = idx >> 4, q = (idx & 15) << 2;
      *(float4*)(Xb + n * 68 + q) = *(const float4*)(Yp + n * 128 + q);
    }
  }

  const int t0 = c * TCH;
  {
    const float* Ap = g_At + (size_t)t0 * 4096;
#pragma unroll
    for (int q = 0; q < 4; ++q)
      *(float4*)(Atr + ks[q] * 68 + js[q]) = *(const float4*)(Ap + ks[q] * 64 + js[q]);
    if (tid < 64)       sIB[tid] = inp[(size_t)t0 * 64 + tid];
    else if (tid < 128) sIB[tid] = Bst[(size_t)t0 * 64 + (tid - 64)];
  }
  float4 pA[4]; float pIB = 0.0f;
  if (TCH > 1){
    const float* An = g_At + (size_t)(t0 + 1) * 4096;
#pragma unroll
    for (int q = 0; q < 4; ++q) pA[q] = *(const float4*)(An + ks[q] * 64 + js[q]);
    if (tid < 64)       pIB = inp[(size_t)(t0 + 1) * 64 + tid];
    else if (tid < 128) pIB = Bst[(size_t)(t0 + 1) * 64 + (tid - 64)];
  }
  __syncthreads();

  int cur = 0;
  for (int s = 0; s < TCH; ++s){
    const int ab = s & 1;
    const float* At  = Atr + ab * (64 * 68);
    const float* ib  = sIB + ab * 128;
    const float* Xin = Xb + cur * (64 * 68);
    float*       Xout= Xb + (cur ^ 1) * (64 * 68);

    if (s + 1 < TCH){
      float* Ad = Atr + (ab ^ 1) * (64 * 68);
#pragma unroll
      for (int q = 0; q < 4; ++q) *(float4*)(Ad + ks[q] * 68 + js[q]) = pA[q];
      if (tid < 128) sIB[(ab ^ 1) * 128 + tid] = pIB;
    }
    if (s + 2 < TCH){
      const float* An = g_At + (size_t)(t0 + s + 2) * 4096;
#pragma unroll
      for (int q = 0; q < 4; ++q) pA[q] = *(const float4*)(An + ks[q] * 64 + js[q]);
      if (tid < 64)       pIB = inp[(size_t)(t0 + s + 2) * 64 + tid];
      else if (tid < 128) pIB = Bst[(size_t)(t0 + s + 2) * 64 + (tid - 64)];
    }

    u64 aL[4], aH[4];
#pragma unroll
    for (int r = 0; r < 4; ++r){ aL[r] = 0; aH[r] = 0; }

#pragma unroll 4
    for (int k = 0; k < klo; ++k){
      float4 avL = *(const float4*)(At + k * 68 + lo0);
      float4 avH = *(const float4*)(At + k * 68 + hi0);
      u64 xv = *(const u64*)(Xin + k * 68 + c0);
      fma2(aL[0], dup2(avL.x), xv);
      fma2(aL[1], dup2(avL.y), xv);
      fma2(aL[2], dup2(avL.z), xv);
      fma2(aL[3], dup2(avL.w), xv);
      fma2(aH[0], dup2(avH.x), xv);
      fma2(aH[1], dup2(avH.y), xv);
      fma2(aH[2], dup2(avH.z), xv);
      fma2(aH[3], dup2(avH.w), xv);
    }
#pragma unroll 4
    for (int k = klo; k < khi; ++k){
      float4 avH = *(const float4*)(At + k * 68 + hi0);
      u64 xv = *(const u64*)(Xin + k * 68 + c0);
      fma2(aH[0], dup2(avH.x), xv);
      fma2(aH[1], dup2(avH.y), xv);
      fma2(aH[2], dup2(avH.z), xv);
      fma2(aH[3], dup2(avH.w), xv);
    }
    {
      u64 ip = pk2(ib[c0], ib[c0 + 1]);
#pragma unroll
      for (int r = 0; r < 4; ++r){
        fma2(aL[r], dup2(ib[64 + lo0 + r]), ip);
        fma2(aH[r], dup2(ib[64 + hi0 + r]), ip);
      }
    }
#pragma unroll
    for (int r = 0; r < 4; ++r){
      *(u64*)(Xout + (lo0 + r) * 68 + c0) = aL[r];
      *(u64*)(Xout + (hi0 + r) * 68 + c0) = aH[r];
    }

    // direct register -> gmem output: out[t][b][n] = X[n][b]
    float lo[8], hi[8];
#pragma unroll
    for (int r = 0; r < 4; ++r){ unpk2(aL[r], lo[r], hi[r]); unpk2(aH[r], lo[4 + r], hi[4 + r]); }
    float* base = out + (size_t)(t0 + s) * 4096 + (size_t)c0 * 64;
    float4 v;
    v.x = lo[0]; v.y = lo[1]; v.z = lo[2]; v.w = lo[3]; *(float4*)(base + lo0)      = v;
    v.x = lo[4]; v.y = lo[5]; v.z = lo[6]; v.w = lo[7]; *(float4*)(base + hi0)      = v;
    v.x = hi[0]; v.y = hi[1]; v.z = hi[2]; v.w = hi[3]; *(float4*)(base + 64 + lo0) = v;
    v.x = hi[4]; v.y = hi[5]; v.z = hi[6]; v.w = hi[7]; *(float4*)(base + 64 + hi0) = v;

    __syncthreads();
    cur ^= 1;
  }
}

// ================= host =================
extern "C" void kernel_launch(void* const* d_in, const int* in_sizes, int n_in,
                              void* d_out, int out_size){
  const float* inp = (const float*)d_in[0];   // (L, B)
  const float* A   = (const float*)d_in[1];   // (L, N, N)
  const float* Bst = (const float*)d_in[2];   // (L, N)
  float* out = (float*)d_out;                 // (L, B, N)

  const int SMEM1 = (2 * 64 * 68 + 2 * 64 * 132 + 256) * 4;  // 103424
  const int SMEMS = (64 * 68 + 64 * 132 + 64 * 68) * 4;      // 68608
  const int SMEM3 = (2 * 64 * 68 + 2 * 64 * 68 + 256) * 4;   // 70656

  cudaFuncSetAttribute(pass1_kernel,    cudaFuncAttributeMaxDynamicSharedMemorySize, SMEM1);
  cudaFuncSetAttribute(scan_all_kernel, cudaFuncAttributeMaxDynamicSharedMemorySize, SMEMS);
  cudaFuncSetAttribute(pass3_kernel,    cudaFuncAttributeMaxDynamicSharedMemorySize, SMEM3);

  prep_kernel<<<L_TOT, 256>>>(A);
  pass1_kernel<<<NCH, 256, SMEM1>>>(inp, Bst);
  scan_all_kernel<<<NCH, 256, SMEMS>>>();
  pass3_kernel<<<NCH, 256, SMEM3>>>(inp, Bst, out);
  bump_gen_kernel<<<1, 1>>>();
}